// round 16
// baseline (speedup 1.0000x reference)
#include <cuda_runtime.h>
#include <cuda_fp16.h>
#include <cstdint>
#include <cstddef>

#define E_DIM 1024
#define FF    4096
#define NEXP  8
#define NTOK  8192
#define HEADS 16
#define DHEAD 64

#define PITCH  144                    /* small engine: 64 halfs + 16B pad */
#define PLANE128 (128 * PITCH)        /* 18432 */

// big engine: 256x128 tile, BK=128, 2-stage mbarrier pipeline, occ 1
#define BPITCH 272                    /* 128 halfs (256B) + 16B pad = 17*16B */
#define BPLANE_A (256 * BPITCH)       /* 69632 */
#define BPLANE_B (128 * BPITCH)       /* 34816 */
#define BIG_STB  (BPLANE_A + BPLANE_B)       /* 104448 */
#define BIG_NSTG 2
#define BIG_SMEM (BIG_NSTG * BIG_STB)        /* 208896 */
// small engine: 128x128 tile, BK=64, 3 stages, occ 2
#define SMALL_SMEM (3 * 2 * PLANE128)        /* 110592 */

// ---------------- scratch (__device__ globals: allocation-free) ----------------
__device__ __half g_x16 [(size_t)NTOK * E_DIM];
__device__ __half g_w1h[(size_t)NEXP * FF * E_DIM];
__device__ __half g_w2h[(size_t)NEXP * E_DIM * FF];
__device__ __half g_ipwh[(size_t)3 * E_DIM * E_DIM];
__device__ __half g_wkT[(size_t)E_DIM * E_DIM];
__device__ __half g_owh[(size_t)E_DIM * E_DIM];
__device__ __half g_h16[(size_t)NEXP * NTOK * FF];
__device__ __half g_eo16[(size_t)NTOK * NEXP * E_DIM];
__device__ __half g_o16[(size_t)NTOK * E_DIM];
__device__ __half g_q16[(size_t)NTOK * E_DIM];
__device__ __half g_qk16[(size_t)NTOK * HEADS * E_DIM];
__device__ __half g_m16[(size_t)NTOK * HEADS * E_DIM];
__device__ float g_zero[E_DIM];

// ---------------- helpers ----------------
__device__ __forceinline__ uint32_t smem_u32(const void* p) {
    uint32_t a;
    asm("{ .reg .u64 t; cvta.to.shared.u64 t, %1; cvt.u32.u64 %0, t; }" : "=r"(a) : "l"(p));
    return a;
}
__device__ __forceinline__ void ldsm4(uint32_t* r, uint32_t a) {
    asm volatile("ldmatrix.sync.aligned.m8n8.x4.shared.b16 {%0,%1,%2,%3}, [%4];"
                 : "=r"(r[0]), "=r"(r[1]), "=r"(r[2]), "=r"(r[3]) : "r"(a));
}
__device__ __forceinline__ void mma16816(float* c, const uint32_t* a, uint32_t b0, uint32_t b1) {
    asm volatile("mma.sync.aligned.m16n8k16.row.col.f32.f16.f16.f32 "
                 "{%0,%1,%2,%3}, {%4,%5,%6,%7}, {%8,%9}, {%0,%1,%2,%3};"
                 : "+f"(c[0]), "+f"(c[1]), "+f"(c[2]), "+f"(c[3])
                 : "r"(a[0]), "r"(a[1]), "r"(a[2]), "r"(a[3]), "r"(b0), "r"(b1));
}
__device__ __forceinline__ void cp16(uint32_t sa, const void* ga) {
    asm volatile("cp.async.cg.shared.global [%0], [%1], 16;" :: "r"(sa), "l"(ga));
}
__device__ __forceinline__ void mbar_init(uint32_t a, uint32_t cnt) {
    asm volatile("mbarrier.init.shared.b64 [%0], %1;" :: "r"(a), "r"(cnt) : "memory");
}
__device__ __forceinline__ void mbar_arrive(uint32_t a) {
    asm volatile("mbarrier.arrive.release.cta.shared::cta.b64 _, [%0];" :: "r"(a) : "memory");
}
__device__ __forceinline__ void cpasync_mbar_arrive_noinc(uint32_t a) {
    asm volatile("cp.async.mbarrier.arrive.noinc.shared.b64 [%0];" :: "r"(a) : "memory");
}
__device__ __forceinline__ void mbar_wait(uint32_t mbar, uint32_t parity) {
    uint32_t done;
    asm volatile("{\n\t.reg .pred p;\n\t"
                 "mbarrier.try_wait.parity.acquire.cta.shared::cta.b64 p, [%1], %2;\n\t"
                 "selp.b32 %0,1,0,p;\n\t}"
                 : "=r"(done) : "r"(mbar), "r"(parity) : "memory");
    if (!done) {
        asm volatile("{\n\t.reg .pred P1;\n\t"
                     "WL%=:\n\t"
                     "mbarrier.try_wait.parity.acquire.cta.shared::cta.b64 P1, [%0], %1, 0x989680;\n\t"
                     "@P1 bra.uni WD%=;\n\t"
                     "bra.uni WL%=;\n\t"
                     "WD%=:\n\t}"
                     :: "r"(mbar), "r"(parity) : "memory");
    }
}

// ============ BIG GEMM: 256x128 tile, BK=128, 2-stage mbarrier pipeline ============
// C[MxN] = A[MxK] * B[NxK]^T + bias ; z batches expert via strides.
template<int RELU>
__global__ __launch_bounds__(256, 1)
void mma_gemm_big(const __half* __restrict__ A_, int lda,
                  const __half* __restrict__ B_, int ldb,
                  const float* __restrict__ bias_,
                  __half* __restrict__ Ch, int ldc, int K,
                  size_t zA, size_t zB, size_t zC, size_t zbias)
{
    extern __shared__ char smem[];
    __shared__ uint64_t bars[2 * BIG_NSTG];          // full[0..1], empty[2..3]
    const uint32_t sb = smem_u32(smem);
    const uint32_t bfull  = smem_u32(&bars[0]);
    const uint32_t bempty = smem_u32(&bars[BIG_NSTG]);

    const int tid  = threadIdx.x;
    const int lane = tid & 31;
    const int wid  = tid >> 5;
    const int wm   = wid & 3;                        // 4 warps M (64 rows each)
    const int wn   = wid >> 2;                       // 2 warps N (64 cols each)
    const size_t m0 = (size_t)blockIdx.y * 256;
    const size_t n0 = (size_t)blockIdx.x * 128;
    const size_t z  = blockIdx.z;

    const __half* A = A_ + z * zA;
    const __half* B = B_ + z * zB;
    const float* bias = bias_ + z * zbias;

    const int ld_row = tid >> 4;                     // 0..15
    const int ld_ch  = tid & 15;                     // 16B chunk within 256B row

    const uint32_t rowA = (uint32_t)(wm * 64 + (lane & 7) + ((lane >> 3) & 1) * 8);
    const uint32_t kcA  = (uint32_t)(lane >> 4);
    const uint32_t rowB = (uint32_t)(wn * 64 + (lane & 7) + (lane >> 4) * 8);
    const uint32_t kcB  = (uint32_t)((lane >> 3) & 1);

    if (tid == 0) {
#pragma unroll
        for (int s = 0; s < BIG_NSTG; ++s) { mbar_init(bfull + 8 * s, 256); mbar_init(bempty + 8 * s, 256); }
    }
    __syncthreads();

    float acc[4][8][4];
#pragma unroll
    for (int i = 0; i < 4; ++i)
#pragma unroll
        for (int j = 0; j < 8; ++j)
#pragma unroll
            for (int k = 0; k < 4; ++k) acc[i][j][k] = 0.f;

    const int KT = K >> 7;                           // BK = 128; K is 1024 or 4096

    auto load_stage = [&](int s, int kt) {
        const int kpos = kt << 7;
        const uint32_t sbase = sb + (uint32_t)s * BIG_STB;
        const uint32_t co = (uint32_t)ld_ch * 16;
        const int ke = kpos + ld_ch * 8;
#pragma unroll
        for (int j = 0; j < 16; ++j) {
            const int row = j * 16 + ld_row;
            cp16(sbase + (uint32_t)row * BPITCH + co, A + (m0 + row) * (size_t)lda + ke);
        }
#pragma unroll
        for (int j = 0; j < 8; ++j) {
            const int row = j * 16 + ld_row;
            cp16(sbase + BPLANE_A + (uint32_t)row * BPITCH + co, B + (n0 + row) * (size_t)ldb + ke);
        }
    };

    // prologue: stage 0 (wrap 0)
    load_stage(0, 0);
    cpasync_mbar_arrive_noinc(bfull + 0);

    for (int kt = 0; kt < KT; ++kt) {
        const int s_cur = kt & 1;
        const int u_cur = kt >> 1;                   // wrap index of this tile
        mbar_wait(bfull + 8 * s_cur, (uint32_t)(u_cur & 1));

        // issue loads for kt+1 before computing
        const int nkt = kt + 1;
        if (nkt < KT) {
            const int ns = nkt & 1;
            const int nu = nkt >> 1;
            if (nu > 0) mbar_wait(bempty + 8 * ns, (uint32_t)((nu - 1) & 1));
            load_stage(ns, nkt);
            cpasync_mbar_arrive_noinc(bfull + 8 * ns);
        }

        const uint32_t stg = sb + (uint32_t)s_cur * BIG_STB;

        // k-steps 0..6: interleaved ldsm/mma
#pragma unroll
        for (int ks = 0; ks < 7; ++ks) {
            uint32_t af[4][4];
#pragma unroll
            for (int mt = 0; mt < 4; ++mt)
                ldsm4(af[mt], stg + (rowA + mt * 16) * BPITCH + ks * 32 + kcA * 16);
#pragma unroll
            for (int nt2 = 0; nt2 < 4; ++nt2) {
                uint32_t rh[4];
                ldsm4(rh, stg + BPLANE_A + (rowB + nt2 * 16) * BPITCH + ks * 32 + kcB * 16);
#pragma unroll
                for (int mt = 0; mt < 4; ++mt) {
                    mma16816(acc[mt][nt2 * 2],     af[mt], rh[0], rh[1]);
                    mma16816(acc[mt][nt2 * 2 + 1], af[mt], rh[2], rh[3]);
                }
            }
        }

        // last k-step: batch reads, release stage early, then MMA tail
        {
            const int ks = 7;
            uint32_t af[4][4], rh[4][4];
#pragma unroll
            for (int mt = 0; mt < 4; ++mt)
                ldsm4(af[mt], stg + (rowA + mt * 16) * BPITCH + ks * 32 + kcA * 16);
#pragma unroll
            for (int nt2 = 0; nt2 < 4; ++nt2)
                ldsm4(rh[nt2], stg + BPLANE_A + (rowB + nt2 * 16) * BPITCH + ks * 32 + kcB * 16);

            mbar_arrive(bempty + 8 * s_cur);

#pragma unroll
            for (int nt2 = 0; nt2 < 4; ++nt2)
#pragma unroll
                for (int mt = 0; mt < 4; ++mt) {
                    mma16816(acc[mt][nt2 * 2],     af[mt], rh[nt2][0], rh[nt2][1]);
                    mma16816(acc[mt][nt2 * 2 + 1], af[mt], rh[nt2][2], rh[nt2][3]);
                }
        }
    }

    // epilogue
#pragma unroll
    for (int mt = 0; mt < 4; ++mt) {
#pragma unroll
        for (int nt = 0; nt < 8; ++nt) {
            const float* c = acc[mt][nt];
            const size_t gm = m0 + wm * 64 + mt * 16 + (lane >> 2);
            const int    gn = (int)n0 + wn * 64 + nt * 8 + (lane & 3) * 2;
            const float b0 = bias[gn], b1 = bias[gn + 1];
#pragma unroll
            for (int half_i = 0; half_i < 2; ++half_i) {
                const size_t row = gm + half_i * 8;
                float v0 = c[half_i * 2 + 0] + b0;
                float v1 = c[half_i * 2 + 1] + b1;
                if (RELU) { v0 = fmaxf(v0, 0.f); v1 = fmaxf(v1, 0.f); }
                *(__half2*)(Ch + z * zC + row * (size_t)ldc + gn) =
                    __halves2half2(__float2half_rn(v0), __float2half_rn(v1));
            }
        }
    }
}

// ============ SMALL GEMM: 128xBN tile, syncthreads 3-stage, occ 2 ============
template<int RELU, int OUT16, int BN>
__global__ __launch_bounds__(256, 2)
void mma_gemm(const __half* __restrict__ A_, int lda,
              const __half* __restrict__ Bh_, int ldb,
              const float* __restrict__ bias_,
              float* __restrict__ C, __half* __restrict__ Ch,
              int ldc, int K,
              const int* __restrict__ aoff, int aoff_mult,
              size_t zA, size_t zB, size_t zC, size_t zbias)
{
    constexpr int NSTG = 3;
    constexpr int NT   = BN / 16;
    constexpr int NT2  = BN / 32;
    constexpr uint32_t PLANE_B = BN * PITCH;
    constexpr uint32_t STB = PLANE128 + PLANE_B;

    extern __shared__ char smem[];
    const uint32_t sb = smem_u32(smem);
    const int tid  = threadIdx.x;
    const int lane = tid & 31;
    const int wid  = tid >> 5;
    const int wm   = wid & 3;
    const int wn   = wid >> 2;
    const size_t m0 = (size_t)blockIdx.y * 128;
    const size_t n0 = (size_t)blockIdx.x * BN;
    const size_t z  = blockIdx.z;

    const __half* A  = A_  + z * zA;
    const __half* Bh = Bh_ + z * zB;
    const float* bias = bias_ + z * zbias;
    if (aoff) A += (size_t)(*aoff) * (size_t)aoff_mult;

    const int ld_row = tid >> 3;
    const int ld_ch  = tid & 7;

    const uint32_t rowA = (uint32_t)(wm * 32 + (lane & 7) + ((lane >> 3) & 1) * 8);
    const uint32_t kcA  = (uint32_t)(lane >> 4);
    const uint32_t rowB = (uint32_t)(wn * (BN / 2) + (lane & 7) + (lane >> 4) * 8);
    const uint32_t kcB  = (uint32_t)((lane >> 3) & 1);

    float acc[2][NT][4];
#pragma unroll
    for (int i = 0; i < 2; ++i)
#pragma unroll
        for (int j = 0; j < NT; ++j)
#pragma unroll
            for (int k = 0; k < 4; ++k) acc[i][j][k] = 0.f;

    const int KT = K >> 6;

    auto load_stage = [&](int s, int kt) {
        const int kpos = kt << 6;
        const uint32_t sbase = sb + (uint32_t)s * STB;
        const uint32_t co = (uint32_t)ld_ch * 16;
        const int ke = kpos + ld_ch * 8;
#pragma unroll
        for (int j = 0; j < 4; ++j) {
            const int row = j * 32 + ld_row;
            cp16(sbase + (uint32_t)row * PITCH + co, A + (m0 + row) * (size_t)lda + ke);
        }
#pragma unroll
        for (int j = 0; j < BN / 32; ++j) {
            const int row = j * 32 + ld_row;
            cp16(sbase + PLANE128 + (uint32_t)row * PITCH + co, Bh + (n0 + row) * (size_t)ldb + ke);
        }
    };

#pragma unroll
    for (int s = 0; s < NSTG - 1; ++s) {
        if (s < KT) load_stage(s, s);
        asm volatile("cp.async.commit_group;" ::: "memory");
    }

    int s_cur = 0, s_load = NSTG - 1;
    for (int kt = 0; kt < KT; ++kt) {
        asm volatile("cp.async.wait_group %0;" :: "n"(NSTG - 2) : "memory");
        __syncthreads();

        const int nkt = kt + NSTG - 1;
        if (nkt < KT) load_stage(s_load, nkt);
        asm volatile("cp.async.commit_group;" ::: "memory");

        const uint32_t stg = sb + (uint32_t)s_cur * STB;
#pragma unroll
        for (int ks = 0; ks < 4; ++ks) {
            uint32_t af[2][4];
#pragma unroll
            for (int mt = 0; mt < 2; ++mt)
                ldsm4(af[mt], stg + (rowA + mt * 16) * PITCH + ks * 32 + kcA * 16);
#pragma unroll
            for (int nt2 = 0; nt2 < NT2; ++nt2) {
                uint32_t rh[4];
                ldsm4(rh, stg + PLANE128 + (rowB + nt2 * 16) * PITCH + ks * 32 + kcB * 16);
#pragma unroll
                for (int mt = 0; mt < 2; ++mt) {
                    mma16816(acc[mt][nt2 * 2],     af[mt], rh[0], rh[1]);
                    mma16816(acc[mt][nt2 * 2 + 1], af[mt], rh[2], rh[3]);
                }
            }
        }

        if (++s_cur == NSTG) s_cur = 0;
        if (++s_load == NSTG) s_load = 0;
    }

#pragma unroll
    for (int mt = 0; mt < 2; ++mt) {
#pragma unroll
        for (int nt = 0; nt < NT; ++nt) {
            const float* c = acc[mt][nt];
            const size_t gm = m0 + wm * 32 + mt * 16 + (lane >> 2);
            const int    gn = (int)n0 + wn * (BN / 2) + nt * 8 + (lane & 3) * 2;
            const float b0 = bias[gn], b1 = bias[gn + 1];
#pragma unroll
            for (int half_i = 0; half_i < 2; ++half_i) {
                const size_t row = gm + half_i * 8;
                float v0 = c[half_i * 2 + 0] + b0;
                float v1 = c[half_i * 2 + 1] + b1;
                if (RELU) { v0 = fmaxf(v0, 0.f); v1 = fmaxf(v1, 0.f); }
                if (OUT16) {
                    *(__half2*)(Ch + z * zC + row * (size_t)ldc + gn) =
                        __halves2half2(__float2half_rn(v0), __float2half_rn(v1));
                } else {
                    *(float2*)(C + z * zC + row * (size_t)ldc + gn) = make_float2(v0, v1);
                }
            }
        }
    }
}

// ---------------- fp32 -> fp16 single-plane ----------------
__global__ void cvt_kernel(const float4* __restrict__ src, __half* __restrict__ dst, int n4)
{
    const int i = blockIdx.x * blockDim.x + threadIdx.x;
    if (i >= n4) return;
    const float4 v = src[i];
    ((__half2*)dst)[2 * i]     = __halves2half2(__float2half_rn(v.x), __float2half_rn(v.y));
    ((__half2*)dst)[2 * i + 1] = __halves2half2(__float2half_rn(v.z), __float2half_rn(v.w));
}

// ---------------- wk transpose (fp32 -> fp16) ----------------
__global__ void transpose_wk_kernel(const float* __restrict__ wk, __half* __restrict__ wkT)
{
    __shared__ float tile[32][33];
    const int bx = blockIdx.x * 32, by = blockIdx.y * 32;
    const int tx = threadIdx.x, ty = threadIdx.y;
#pragma unroll
    for (int i = 0; i < 32; i += 8)
        tile[ty + i][tx] = wk[(size_t)(by + ty + i) * E_DIM + bx + tx];
    __syncthreads();
#pragma unroll
    for (int i = 0; i < 32; i += 8)
        wkT[(size_t)(bx + ty + i) * E_DIM + by + tx] = __float2half_rn(tile[tx][ty + i]);
}

// ---------------- attention: logits via qk.eo + qb, softmax, eo mixing ----------------
__global__ __launch_bounds__(512)
void attn_mix_kernel(const __half* __restrict__ qk,
                     const __half* __restrict__ q16,
                     const __half* __restrict__ eo,
                     const float* __restrict__ ipb,
                     __half* __restrict__ m16,
                     const int* __restrict__ expert_id)
{
    __shared__ __half eo_s[NEXP * E_DIM];
    const int t    = blockIdx.x;
    const int tid  = threadIdx.x;
    const int h    = tid >> 5;
    const int lane = tid & 31;
    const int eid  = *expert_id;

    {
        const uint4* src = (const uint4*)(eo + (size_t)t * (NEXP * E_DIM));
        uint4* dst = (uint4*)eo_s;
        for (int i = tid; i < 1024; i += 512) dst[i] = src[i];
    }

    __half2 qkr[16];
    {
        const __half* qr = qk + ((size_t)t * HEADS + h) * E_DIM + 2 * lane;
#pragma unroll
        for (int j = 0; j < 16; ++j) qkr[j] = *(const __half2*)(qr + 64 * j);
    }

    float qb;
    {
        const __half2 qv = *(const __half2*)(q16 + (size_t)t * E_DIM + h * DHEAD + 2 * lane);
        qb = __low2float(qv)  * ipb[E_DIM + h * DHEAD + 2 * lane]
           + __high2float(qv) * ipb[E_DIM + h * DHEAD + 2 * lane + 1];
    }
#pragma unroll
    for (int off = 16; off; off >>= 1) qb += __shfl_xor_sync(0xffffffffu, qb, off);

    __syncthreads();

    float sarr[NEXP];
#pragma unroll
    for (int n = 0; n < NEXP; ++n) {
        float s = 0.f;
        const __half* er = eo_s + n * E_DIM + 2 * lane;
#pragma unroll
        for (int j = 0; j < 16; ++j) {
            const __half2 e2 = *(const __half2*)(er + 64 * j);
            s = fmaf(__low2float(qkr[j]),  __low2float(e2),  s);
            s = fmaf(__high2float(qkr[j]), __high2float(e2), s);
        }
#pragma unroll
        for (int off = 16; off; off >>= 1) s += __shfl_xor_sync(0xffffffffu, s, off);
        sarr[n] = s;
    }

    float lg = -1e30f;
#pragma unroll
    for (int n = 0; n < NEXP; ++n)
        if (lane == n) lg = (sarr[n] + qb) * 0.125f + (n <= eid ? 1.f : 0.f);

    float mx = lg;
#pragma unroll
    for (int off = 4; off; off >>= 1) mx = fmaxf(mx, __shfl_xor_sync(0xffffffffu, mx, off));
    float e = (lane < NEXP) ? expf(lg - mx) : 0.f;
    float se = e;
#pragma unroll
    for (int off = 4; off; off >>= 1) se += __shfl_xor_sync(0xffffffffu, se, off);
    const float p = e / se;

    float a[NEXP];
#pragma unroll
    for (int n = 0; n < NEXP; ++n) a[n] = __shfl_sync(0xffffffffu, p, n);

    __half* mr = m16 + ((size_t)t * HEADS + h) * E_DIM;
#pragma unroll 4
    for (int i = 0; i < E_DIM / 64; ++i) {
        const int e0 = i * 64 + lane * 2;
        float s0 = 0.f, s1 = 0.f;
#pragma unroll
        for (int n = 0; n < NEXP; ++n) {
            const __half2 v2 = *(const __half2*)(eo_s + n * E_DIM + e0);
            s0 = fmaf(a[n], __low2float(v2),  s0);
            s1 = fmaf(a[n], __high2float(v2), s1);
        }
        *(__half2*)(mr + e0) = __halves2half2(__float2half_rn(s0), __float2half_rn(s1));
    }
}

// ---------------- host ----------------
static void run_cvt(const float* src, __half* dst, size_t n) {
    const int n4 = (int)(n / 4);
    cvt_kernel<<<(n4 + 255) / 256, 256>>>((const float4*)src, dst, n4);
}

extern "C" void kernel_launch(void* const* d_in, const int* in_sizes, int n_in,
                              void* d_out, int out_size)
{
    const float* x   = (const float*)d_in[0];
    const float* w1  = (const float*)d_in[1];
    const float* b1  = (const float*)d_in[2];
    const float* w2  = (const float*)d_in[3];
    const float* b2  = (const float*)d_in[4];
    const float* ipw = (const float*)d_in[5];
    const float* ipb = (const float*)d_in[6];
    const float* ow  = (const float*)d_in[7];
    const float* ob  = (const float*)d_in[8];
    const int*   eid = (const int*)d_in[9];
    float* out = (float*)d_out;

    cudaFuncSetAttribute(mma_gemm_big<1>, cudaFuncAttributeMaxDynamicSharedMemorySize, BIG_SMEM);
    cudaFuncSetAttribute(mma_gemm_big<0>, cudaFuncAttributeMaxDynamicSharedMemorySize, BIG_SMEM);
    cudaFuncSetAttribute(mma_gemm<0, 1, 128>, cudaFuncAttributeMaxDynamicSharedMemorySize, SMALL_SMEM);
    cudaFuncSetAttribute(mma_gemm<0, 0, 128>, cudaFuncAttributeMaxDynamicSharedMemorySize, SMALL_SMEM);
    cudaFuncSetAttribute(mma_gemm<0, 1, 64>,
                         cudaFuncAttributeMaxDynamicSharedMemorySize, 3 * (PLANE128 + 64 * PITCH));

    void *p;
    cudaGetSymbolAddress(&p, g_x16); __half* x16 = (__half*)p;
    cudaGetSymbolAddress(&p, g_w1h); __half* w1h = (__half*)p;
    cudaGetSymbolAddress(&p, g_w2h); __half* w2h = (__half*)p;
    cudaGetSymbolAddress(&p, g_ipwh);__half* ipwh= (__half*)p;
    cudaGetSymbolAddress(&p, g_wkT); __half* wkT = (__half*)p;
    cudaGetSymbolAddress(&p, g_owh); __half* owh = (__half*)p;
    cudaGetSymbolAddress(&p, g_h16); __half* h16 = (__half*)p;
    cudaGetSymbolAddress(&p, g_eo16);__half* eo16= (__half*)p;
    cudaGetSymbolAddress(&p, g_o16); __half* o16 = (__half*)p;
    cudaGetSymbolAddress(&p, g_q16); __half* q16 = (__half*)p;
    cudaGetSymbolAddress(&p, g_qk16);__half* qk16= (__half*)p;
    cudaGetSymbolAddress(&p, g_m16); __half* m16 = (__half*)p;
    cudaGetSymbolAddress(&p, g_zero);float* zerob= (float*)p;

    const dim3 blk(256);

    run_cvt(x,  x16, (size_t)NTOK * E_DIM);
    run_cvt(w1, w1h, (size_t)NEXP * FF * E_DIM);
    run_cvt(w2, w2h, (size_t)NEXP * E_DIM * FF);

    // FFN stage 1 (big BK=128 engine, z = expert)
    mma_gemm_big<1><<<dim3(FF / 128, NTOK / 256, NEXP), blk, BIG_SMEM>>>(
        x16, E_DIM, w1h, E_DIM, b1,
        h16, FF, E_DIM,
        0, (size_t)FF * E_DIM, (size_t)NTOK * FF, FF);

    run_cvt(ipw, ipwh, (size_t)3 * E_DIM * E_DIM);

    // FFN stage 2 (big BK=128 engine, z = expert); eo expert-interleaved
    mma_gemm_big<0><<<dim3(E_DIM / 128, NTOK / 256, NEXP), blk, BIG_SMEM>>>(
        h16, FF, w2h, FF, b2,
        eo16, NEXP * E_DIM, FF,
        (size_t)NTOK * FF, (size_t)E_DIM * FF, (size_t)E_DIM, E_DIM);

    transpose_wk_kernel<<<dim3(32, 32), dim3(32, 8)>>>(ipw + (size_t)E_DIM * E_DIM, wkT);

    // q projection for expert_id slice only (fp16 out)
    mma_gemm<0, 1, 128><<<dim3(E_DIM / 128, NTOK / 128, 1), blk, SMALL_SMEM>>>(
        eo16, NEXP * E_DIM, ipwh, E_DIM, ipb,
        nullptr, q16, E_DIM, E_DIM, eid, E_DIM, 0, 0, 0, 0);

    // qk[t,h,:] = q[t,h,:] @ wk_h  (z = head, K = 64)
    mma_gemm<0, 1, 128><<<dim3(E_DIM / 128, NTOK / 128, HEADS), blk, SMALL_SMEM>>>(
        q16, E_DIM, wkT, E_DIM, zerob,
        nullptr, qk16, HEADS * E_DIM, DHEAD, nullptr, 0,
        (size_t)DHEAD, (size_t)DHEAD, (size_t)E_DIM, 0);

    // attention: logits = (qk.eo + q.bk)*scale + mask; softmax; mix -> m[t,h,:]
    attn_mix_kernel<<<NTOK, 512>>>(qk16, q16, eo16, ipb, m16, eid);

    // block-diagonal v projection: o[t, h*64+d] = m[t,h,:] @ wv_h^T + bv_h  (z = head)
    mma_gemm<0, 1, 64><<<dim3(1, NTOK / 128, HEADS), blk, 3 * (PLANE128 + 64 * PITCH)>>>(
        m16, HEADS * E_DIM,
        ipwh + (size_t)2 * E_DIM * E_DIM, E_DIM, ipb + 2 * E_DIM,
        nullptr, o16, E_DIM, E_DIM, nullptr, 0,
        (size_t)E_DIM, (size_t)DHEAD * E_DIM, (size_t)DHEAD, DHEAD);

    run_cvt(ow, owh, (size_t)E_DIM * E_DIM);

    // output projection -> d_out (fp32)
    mma_gemm<0, 0, 128><<<dim3(E_DIM / 128, NTOK / 128, 1), blk, SMALL_SMEM>>>(
        o16, E_DIM, owh, E_DIM, ob,
        out, nullptr, E_DIM, E_DIM, nullptr, 0, 0, 0, 0, 0);
}

// round 17
// speedup vs baseline: 1.0954x; 1.0954x over previous
#include <cuda_runtime.h>
#include <cuda_fp16.h>
#include <cstdint>
#include <cstddef>

#define E_DIM 1024
#define FF    4096
#define NEXP  8
#define NTOK  8192
#define HEADS 16
#define DHEAD 64

#define PITCH 144                     /* 64*2B + 16B pad */
#define PLANE128 (128 * PITCH)        /* 18432 */
#define PLANE256 (256 * PITCH)        /* 36864 */

// big engine: 256x128 tile, 3-stage mbarrier pipeline, occ 1
#define BIG_STB   (PLANE256 + PLANE128)      /* 55296 */
#define BIG_NSTG  3
#define BIG_SMEM  (BIG_NSTG * BIG_STB)       /* 165888 */
// small engine: 128x128 tile, 3 stages, occ 2
#define SMALL_SMEM (3 * 2 * PLANE128)        /* 110592 */

// ---------------- scratch (__device__ globals: allocation-free) ----------------
__device__ __half g_x16 [(size_t)NTOK * E_DIM];
__device__ __half g_w1h[(size_t)NEXP * FF * E_DIM];
__device__ __half g_w2h[(size_t)NEXP * E_DIM * FF];
__device__ __half g_ipwh[(size_t)3 * E_DIM * E_DIM];
__device__ __half g_wkT[(size_t)E_DIM * E_DIM];
__device__ __half g_owh[(size_t)E_DIM * E_DIM];
__device__ __half g_h16[(size_t)NEXP * NTOK * FF];
__device__ __half g_eo16[(size_t)NTOK * NEXP * E_DIM];
__device__ __half g_o16[(size_t)NTOK * E_DIM];
__device__ __half g_q16[(size_t)NTOK * E_DIM];
__device__ __half g_qk16[(size_t)NTOK * HEADS * E_DIM];
__device__ __half g_m16[(size_t)NTOK * HEADS * E_DIM];
__device__ float g_zero[E_DIM];

// ---------------- helpers ----------------
__device__ __forceinline__ uint32_t smem_u32(const void* p) {
    uint32_t a;
    asm("{ .reg .u64 t; cvta.to.shared.u64 t, %1; cvt.u32.u64 %0, t; }" : "=r"(a) : "l"(p));
    return a;
}
__device__ __forceinline__ void ldsm4(uint32_t* r, uint32_t a) {
    asm volatile("ldmatrix.sync.aligned.m8n8.x4.shared.b16 {%0,%1,%2,%3}, [%4];"
                 : "=r"(r[0]), "=r"(r[1]), "=r"(r[2]), "=r"(r[3]) : "r"(a));
}
__device__ __forceinline__ void mma16816(float* c, const uint32_t* a, uint32_t b0, uint32_t b1) {
    asm volatile("mma.sync.aligned.m16n8k16.row.col.f32.f16.f16.f32 "
                 "{%0,%1,%2,%3}, {%4,%5,%6,%7}, {%8,%9}, {%0,%1,%2,%3};"
                 : "+f"(c[0]), "+f"(c[1]), "+f"(c[2]), "+f"(c[3])
                 : "r"(a[0]), "r"(a[1]), "r"(a[2]), "r"(a[3]), "r"(b0), "r"(b1));
}
__device__ __forceinline__ void cp16(uint32_t sa, const void* ga) {
    asm volatile("cp.async.cg.shared.global [%0], [%1], 16;" :: "r"(sa), "l"(ga));
}
__device__ __forceinline__ void mbar_init(uint32_t a, uint32_t cnt) {
    asm volatile("mbarrier.init.shared.b64 [%0], %1;" :: "r"(a), "r"(cnt) : "memory");
}
__device__ __forceinline__ void mbar_arrive(uint32_t a) {
    asm volatile("mbarrier.arrive.shared.b64 _, [%0];" :: "r"(a) : "memory");
}
__device__ __forceinline__ void cpasync_mbar_arrive_noinc(uint32_t a) {
    asm volatile("cp.async.mbarrier.arrive.noinc.shared.b64 [%0];" :: "r"(a) : "memory");
}
__device__ __forceinline__ void mbar_wait(uint32_t mbar, uint32_t parity) {
    uint32_t done;
    asm volatile("{\n\t.reg .pred p;\n\t"
                 "mbarrier.try_wait.parity.acquire.cta.shared::cta.b64 p, [%1], %2;\n\t"
                 "selp.b32 %0,1,0,p;\n\t}"
                 : "=r"(done) : "r"(mbar), "r"(parity) : "memory");
    if (!done) {
        asm volatile("{\n\t.reg .pred P1;\n\t"
                     "WL%=:\n\t"
                     "mbarrier.try_wait.parity.acquire.cta.shared::cta.b64 P1, [%0], %1, 0x989680;\n\t"
                     "@P1 bra.uni WD%=;\n\t"
                     "bra.uni WL%=;\n\t"
                     "WD%=:\n\t}"
                     :: "r"(mbar), "r"(parity) : "memory");
    }
}

// ============ BIG GEMM: 256x128 tile, 3-stage mbarrier pipeline, occ 1 ============
// C[MxN] = A[MxK] * B[NxK]^T + bias ; z batches expert via strides.
template<int RELU>
__global__ __launch_bounds__(256, 1)
void mma_gemm_big(const __half* __restrict__ A_, int lda,
                  const __half* __restrict__ B_, int ldb,
                  const float* __restrict__ bias_,
                  __half* __restrict__ Ch, int ldc, int K,
                  size_t zA, size_t zB, size_t zC, size_t zbias)
{
    extern __shared__ char smem[];
    __shared__ uint64_t bars[2 * BIG_NSTG];          // full[0..2], empty[3..5]
    const uint32_t sb = smem_u32(smem);
    const uint32_t bfull  = smem_u32(&bars[0]);
    const uint32_t bempty = smem_u32(&bars[BIG_NSTG]);

    const int tid  = threadIdx.x;
    const int lane = tid & 31;
    const int wid  = tid >> 5;
    const int wm   = wid & 3;                        // 4 warps M (64 rows each)
    const int wn   = wid >> 2;                       // 2 warps N (64 cols each)
    const size_t m0 = (size_t)blockIdx.y * 256;
    const size_t n0 = (size_t)blockIdx.x * 128;
    const size_t z  = blockIdx.z;

    const __half* A = A_ + z * zA;
    const __half* B = B_ + z * zB;
    const float* bias = bias_ + z * zbias;

    const int ld_row = tid >> 3;                     // 0..31
    const int ld_ch  = tid & 7;                      // 16B chunk

    const uint32_t rowA = (uint32_t)(wm * 64 + (lane & 7) + ((lane >> 3) & 1) * 8);
    const uint32_t kcA  = (uint32_t)(lane >> 4);
    const uint32_t rowB = (uint32_t)(wn * 64 + (lane & 7) + (lane >> 4) * 8);
    const uint32_t kcB  = (uint32_t)((lane >> 3) & 1);

    if (tid == 0) {
#pragma unroll
        for (int s = 0; s < BIG_NSTG; ++s) { mbar_init(bfull + 8 * s, 256); mbar_init(bempty + 8 * s, 256); }
    }
    __syncthreads();

    float acc[4][8][4];
#pragma unroll
    for (int i = 0; i < 4; ++i)
#pragma unroll
        for (int j = 0; j < 8; ++j)
#pragma unroll
            for (int k = 0; k < 4; ++k) acc[i][j][k] = 0.f;

    const int KT = K >> 6;                           // BK = 64; KT >= 16 for all big uses

    auto load_stage = [&](int s, int kt) {
        const int kpos = kt << 6;
        const uint32_t sbase = sb + (uint32_t)s * BIG_STB;
        const uint32_t co = (uint32_t)ld_ch * 16;
        const int ke = kpos + ld_ch * 8;
#pragma unroll
        for (int j = 0; j < 8; ++j) {
            const int row = j * 32 + ld_row;
            cp16(sbase + (uint32_t)row * PITCH + co, A + (m0 + row) * (size_t)lda + ke);
        }
#pragma unroll
        for (int j = 0; j < 4; ++j) {
            const int row = j * 32 + ld_row;
            cp16(sbase + PLANE256 + (uint32_t)row * PITCH + co, B + (n0 + row) * (size_t)ldb + ke);
        }
    };

    // prologue: stages 0,1 (wrap 0)
#pragma unroll
    for (int s = 0; s < BIG_NSTG - 1; ++s) {
        load_stage(s, s);
        cpasync_mbar_arrive_noinc(bfull + 8 * s);
    }

    for (int kt = 0; kt < KT; ++kt) {
        const int s_cur = kt % BIG_NSTG;
        const int u_cur = kt / BIG_NSTG;             // wrap index of this tile
        mbar_wait(bfull + 8 * s_cur, (uint32_t)(u_cur & 1));

        // issue loads for kt + NSTG-1 before computing (hides DMA latency)
        const int nkt = kt + BIG_NSTG - 1;
        if (nkt < KT) {
            const int ns = nkt % BIG_NSTG;
            const int nu = nkt / BIG_NSTG;
            if (nu > 0) mbar_wait(bempty + 8 * ns, (uint32_t)((nu - 1) & 1));
            load_stage(ns, nkt);
            cpasync_mbar_arrive_noinc(bfull + 8 * ns);
        }

        const uint32_t stg = sb + (uint32_t)s_cur * BIG_STB;
        const uint32_t bbase = stg + PLANE256;

#pragma unroll
        for (int ks = 0; ks < 4; ++ks) {
            uint32_t af[4][4];
            uint32_t rh[2][4];                        // B-fragment double buffer
#pragma unroll
            for (int mt = 0; mt < 4; ++mt)
                ldsm4(af[mt], stg + (rowA + mt * 16) * PITCH + ks * 32 + kcA * 16);

            // prefetch B fragment for nt2 = 0
            ldsm4(rh[0], bbase + rowB * PITCH + ks * 32 + kcB * 16);

#pragma unroll
            for (int nt2 = 0; nt2 < 4; ++nt2) {
                const int cur = nt2 & 1;
                if (nt2 < 3)                         // prefetch next B fragment
                    ldsm4(rh[cur ^ 1], bbase + (rowB + (nt2 + 1) * 16) * PITCH + ks * 32 + kcB * 16);
#pragma unroll
                for (int mt = 0; mt < 4; ++mt) {
                    mma16816(acc[mt][nt2 * 2],     af[mt], rh[cur][0], rh[cur][1]);
                    mma16816(acc[mt][nt2 * 2 + 1], af[mt], rh[cur][2], rh[cur][3]);
                }
            }
        }
        mbar_arrive(bempty + 8 * s_cur);
    }

    // epilogue
#pragma unroll
    for (int mt = 0; mt < 4; ++mt) {
#pragma unroll
        for (int nt = 0; nt < 8; ++nt) {
            const float* c = acc[mt][nt];
            const size_t gm = m0 + wm * 64 + mt * 16 + (lane >> 2);
            const int    gn = (int)n0 + wn * 64 + nt * 8 + (lane & 3) * 2;
            const float b0 = bias[gn], b1 = bias[gn + 1];
#pragma unroll
            for (int half_i = 0; half_i < 2; ++half_i) {
                const size_t row = gm + half_i * 8;
                float v0 = c[half_i * 2 + 0] + b0;
                float v1 = c[half_i * 2 + 1] + b1;
                if (RELU) { v0 = fmaxf(v0, 0.f); v1 = fmaxf(v1, 0.f); }
                *(__half2*)(Ch + z * zC + row * (size_t)ldc + gn) =
                    __halves2half2(__float2half_rn(v0), __float2half_rn(v1));
            }
        }
    }
}

// ============ SMALL GEMM: 128xBN tile, syncthreads 3-stage, occ 2 ============
template<int RELU, int OUT16, int BN>
__global__ __launch_bounds__(256, 2)
void mma_gemm(const __half* __restrict__ A_, int lda,
              const __half* __restrict__ Bh_, int ldb,
              const float* __restrict__ bias_,
              float* __restrict__ C, __half* __restrict__ Ch,
              int ldc, int K,
              const int* __restrict__ aoff, int aoff_mult,
              size_t zA, size_t zB, size_t zC, size_t zbias)
{
    constexpr int NSTG = 3;
    constexpr int NT   = BN / 16;
    constexpr int NT2  = BN / 32;
    constexpr uint32_t PLANE_B = BN * PITCH;
    constexpr uint32_t STB = PLANE128 + PLANE_B;

    extern __shared__ char smem[];
    const uint32_t sb = smem_u32(smem);
    const int tid  = threadIdx.x;
    const int lane = tid & 31;
    const int wid  = tid >> 5;
    const int wm   = wid & 3;
    const int wn   = wid >> 2;
    const size_t m0 = (size_t)blockIdx.y * 128;
    const size_t n0 = (size_t)blockIdx.x * BN;
    const size_t z  = blockIdx.z;

    const __half* A  = A_  + z * zA;
    const __half* Bh = Bh_ + z * zB;
    const float* bias = bias_ + z * zbias;
    if (aoff) A += (size_t)(*aoff) * (size_t)aoff_mult;

    const int ld_row = tid >> 3;
    const int ld_ch  = tid & 7;

    const uint32_t rowA = (uint32_t)(wm * 32 + (lane & 7) + ((lane >> 3) & 1) * 8);
    const uint32_t kcA  = (uint32_t)(lane >> 4);
    const uint32_t rowB = (uint32_t)(wn * (BN / 2) + (lane & 7) + (lane >> 4) * 8);
    const uint32_t kcB  = (uint32_t)((lane >> 3) & 1);

    float acc[2][NT][4];
#pragma unroll
    for (int i = 0; i < 2; ++i)
#pragma unroll
        for (int j = 0; j < NT; ++j)
#pragma unroll
            for (int k = 0; k < 4; ++k) acc[i][j][k] = 0.f;

    const int KT = K >> 6;

    auto load_stage = [&](int s, int kt) {
        const int kpos = kt << 6;
        const uint32_t sbase = sb + (uint32_t)s * STB;
        const uint32_t co = (uint32_t)ld_ch * 16;
        const int ke = kpos + ld_ch * 8;
#pragma unroll
        for (int j = 0; j < 4; ++j) {
            const int row = j * 32 + ld_row;
            cp16(sbase + (uint32_t)row * PITCH + co, A + (m0 + row) * (size_t)lda + ke);
        }
#pragma unroll
        for (int j = 0; j < BN / 32; ++j) {
            const int row = j * 32 + ld_row;
            cp16(sbase + PLANE128 + (uint32_t)row * PITCH + co, Bh + (n0 + row) * (size_t)ldb + ke);
        }
    };

#pragma unroll
    for (int s = 0; s < NSTG - 1; ++s) {
        if (s < KT) load_stage(s, s);
        asm volatile("cp.async.commit_group;" ::: "memory");
    }

    int s_cur = 0, s_load = NSTG - 1;
    for (int kt = 0; kt < KT; ++kt) {
        asm volatile("cp.async.wait_group %0;" :: "n"(NSTG - 2) : "memory");
        __syncthreads();

        const int nkt = kt + NSTG - 1;
        if (nkt < KT) load_stage(s_load, nkt);
        asm volatile("cp.async.commit_group;" ::: "memory");

        const uint32_t stg = sb + (uint32_t)s_cur * STB;
#pragma unroll
        for (int ks = 0; ks < 4; ++ks) {
            uint32_t af[2][4];
#pragma unroll
            for (int mt = 0; mt < 2; ++mt)
                ldsm4(af[mt], stg + (rowA + mt * 16) * PITCH + ks * 32 + kcA * 16);
#pragma unroll
            for (int nt2 = 0; nt2 < NT2; ++nt2) {
                uint32_t rh[4];
                ldsm4(rh, stg + PLANE128 + (rowB + nt2 * 16) * PITCH + ks * 32 + kcB * 16);
#pragma unroll
                for (int mt = 0; mt < 2; ++mt) {
                    mma16816(acc[mt][nt2 * 2],     af[mt], rh[0], rh[1]);
                    mma16816(acc[mt][nt2 * 2 + 1], af[mt], rh[2], rh[3]);
                }
            }
        }

        if (++s_cur == NSTG) s_cur = 0;
        if (++s_load == NSTG) s_load = 0;
    }

#pragma unroll
    for (int mt = 0; mt < 2; ++mt) {
#pragma unroll
        for (int nt = 0; nt < NT; ++nt) {
            const float* c = acc[mt][nt];
            const size_t gm = m0 + wm * 32 + mt * 16 + (lane >> 2);
            const int    gn = (int)n0 + wn * (BN / 2) + nt * 8 + (lane & 3) * 2;
            const float b0 = bias[gn], b1 = bias[gn + 1];
#pragma unroll
            for (int half_i = 0; half_i < 2; ++half_i) {
                const size_t row = gm + half_i * 8;
                float v0 = c[half_i * 2 + 0] + b0;
                float v1 = c[half_i * 2 + 1] + b1;
                if (RELU) { v0 = fmaxf(v0, 0.f); v1 = fmaxf(v1, 0.f); }
                if (OUT16) {
                    *(__half2*)(Ch + z * zC + row * (size_t)ldc + gn) =
                        __halves2half2(__float2half_rn(v0), __float2half_rn(v1));
                } else {
                    *(float2*)(C + z * zC + row * (size_t)ldc + gn) = make_float2(v0, v1);
                }
            }
        }
    }
}

// ---------------- fp32 -> fp16 single-plane ----------------
__global__ void cvt_kernel(const float4* __restrict__ src, __half* __restrict__ dst, int n4)
{
    const int i = blockIdx.x * blockDim.x + threadIdx.x;
    if (i >= n4) return;
    const float4 v = src[i];
    ((__half2*)dst)[2 * i]     = __halves2half2(__float2half_rn(v.x), __float2half_rn(v.y));
    ((__half2*)dst)[2 * i + 1] = __halves2half2(__float2half_rn(v.z), __float2half_rn(v.w));
}

// ---------------- wk transpose (fp32 -> fp16) ----------------
__global__ void transpose_wk_kernel(const float* __restrict__ wk, __half* __restrict__ wkT)
{
    __shared__ float tile[32][33];
    const int bx = blockIdx.x * 32, by = blockIdx.y * 32;
    const int tx = threadIdx.x, ty = threadIdx.y;
#pragma unroll
    for (int i = 0; i < 32; i += 8)
        tile[ty + i][tx] = wk[(size_t)(by + ty + i) * E_DIM + bx + tx];
    __syncthreads();
#pragma unroll
    for (int i = 0; i < 32; i += 8)
        wkT[(size_t)(bx + ty + i) * E_DIM + by + tx] = __float2half_rn(tile[tx][ty + i]);
}

// ---------------- attention: logits via qk.eo + qb, softmax, eo mixing ----------------
__global__ __launch_bounds__(512)
void attn_mix_kernel(const __half* __restrict__ qk,
                     const __half* __restrict__ q16,
                     const __half* __restrict__ eo,
                     const float* __restrict__ ipb,
                     __half* __restrict__ m16,
                     const int* __restrict__ expert_id)
{
    __shared__ __half eo_s[NEXP * E_DIM];
    const int t    = blockIdx.x;
    const int tid  = threadIdx.x;
    const int h    = tid >> 5;
    const int lane = tid & 31;
    const int eid  = *expert_id;

    {
        const uint4* src = (const uint4*)(eo + (size_t)t * (NEXP * E_DIM));
        uint4* dst = (uint4*)eo_s;
        for (int i = tid; i < 1024; i += 512) dst[i] = src[i];
    }

    __half2 qkr[16];
    {
        const __half* qr = qk + ((size_t)t * HEADS + h) * E_DIM + 2 * lane;
#pragma unroll
        for (int j = 0; j < 16; ++j) qkr[j] = *(const __half2*)(qr + 64 * j);
    }

    float qb;
    {
        const __half2 qv = *(const __half2*)(q16 + (size_t)t * E_DIM + h * DHEAD + 2 * lane);
        qb = __low2float(qv)  * ipb[E_DIM + h * DHEAD + 2 * lane]
           + __high2float(qv) * ipb[E_DIM + h * DHEAD + 2 * lane + 1];
    }
#pragma unroll
    for (int off = 16; off; off >>= 1) qb += __shfl_xor_sync(0xffffffffu, qb, off);

    __syncthreads();

    float sarr[NEXP];
#pragma unroll
    for (int n = 0; n < NEXP; ++n) {
        float s = 0.f;
        const __half* er = eo_s + n * E_DIM + 2 * lane;
#pragma unroll
        for (int j = 0; j < 16; ++j) {
            const __half2 e2 = *(const __half2*)(er + 64 * j);
            s = fmaf(__low2float(qkr[j]),  __low2float(e2),  s);
            s = fmaf(__high2float(qkr[j]), __high2float(e2), s);
        }
#pragma unroll
        for (int off = 16; off; off >>= 1) s += __shfl_xor_sync(0xffffffffu, s, off);
        sarr[n] = s;
    }

    float lg = -1e30f;
#pragma unroll
    for (int n = 0; n < NEXP; ++n)
        if (lane == n) lg = (sarr[n] + qb) * 0.125f + (n <= eid ? 1.f : 0.f);

    float mx = lg;
#pragma unroll
    for (int off = 4; off; off >>= 1) mx = fmaxf(mx, __shfl_xor_sync(0xffffffffu, mx, off));
    float e = (lane < NEXP) ? expf(lg - mx) : 0.f;
    float se = e;
#pragma unroll
    for (int off = 4; off; off >>= 1) se += __shfl_xor_sync(0xffffffffu, se, off);
    const float p = e / se;

    float a[NEXP];
#pragma unroll
    for (int n = 0; n < NEXP; ++n) a[n] = __shfl_sync(0xffffffffu, p, n);

    __half* mr = m16 + ((size_t)t * HEADS + h) * E_DIM;
#pragma unroll 4
    for (int i = 0; i < E_DIM / 64; ++i) {
        const int e0 = i * 64 + lane * 2;
        float s0 = 0.f, s1 = 0.f;
#pragma unroll
        for (int n = 0; n < NEXP; ++n) {
            const __half2 v2 = *(const __half2*)(eo_s + n * E_DIM + e0);
            s0 = fmaf(a[n], __low2float(v2),  s0);
            s1 = fmaf(a[n], __high2float(v2), s1);
        }
        *(__half2*)(mr + e0) = __halves2half2(__float2half_rn(s0), __float2half_rn(s1));
    }
}

// ---------------- host ----------------
static void run_cvt(const float* src, __half* dst, size_t n) {
    const int n4 = (int)(n / 4);
    cvt_kernel<<<(n4 + 255) / 256, 256>>>((const float4*)src, dst, n4);
}

extern "C" void kernel_launch(void* const* d_in, const int* in_sizes, int n_in,
                              void* d_out, int out_size)
{
    const float* x   = (const float*)d_in[0];
    const float* w1  = (const float*)d_in[1];
    const float* b1  = (const float*)d_in[2];
    const float* w2  = (const float*)d_in[3];
    const float* b2  = (const float*)d_in[4];
    const float* ipw = (const float*)d_in[5];
    const float* ipb = (const float*)d_in[6];
    const float* ow  = (const float*)d_in[7];
    const float* ob  = (const float*)d_in[8];
    const int*   eid = (const int*)d_in[9];
    float* out = (float*)d_out;

    cudaFuncSetAttribute(mma_gemm_big<1>, cudaFuncAttributeMaxDynamicSharedMemorySize, BIG_SMEM);
    cudaFuncSetAttribute(mma_gemm_big<0>, cudaFuncAttributeMaxDynamicSharedMemorySize, BIG_SMEM);
    cudaFuncSetAttribute(mma_gemm<0, 1, 128>, cudaFuncAttributeMaxDynamicSharedMemorySize, SMALL_SMEM);
    cudaFuncSetAttribute(mma_gemm<0, 0, 128>, cudaFuncAttributeMaxDynamicSharedMemorySize, SMALL_SMEM);
    cudaFuncSetAttribute(mma_gemm<0, 1, 64>,
                         cudaFuncAttributeMaxDynamicSharedMemorySize, 3 * (PLANE128 + 64 * PITCH));

    void *p;
    cudaGetSymbolAddress(&p, g_x16); __half* x16 = (__half*)p;
    cudaGetSymbolAddress(&p, g_w1h); __half* w1h = (__half*)p;
    cudaGetSymbolAddress(&p, g_w2h); __half* w2h = (__half*)p;
    cudaGetSymbolAddress(&p, g_ipwh);__half* ipwh= (__half*)p;
    cudaGetSymbolAddress(&p, g_wkT); __half* wkT = (__half*)p;
    cudaGetSymbolAddress(&p, g_owh); __half* owh = (__half*)p;
    cudaGetSymbolAddress(&p, g_h16); __half* h16 = (__half*)p;
    cudaGetSymbolAddress(&p, g_eo16);__half* eo16= (__half*)p;
    cudaGetSymbolAddress(&p, g_o16); __half* o16 = (__half*)p;
    cudaGetSymbolAddress(&p, g_q16); __half* q16 = (__half*)p;
    cudaGetSymbolAddress(&p, g_qk16);__half* qk16= (__half*)p;
    cudaGetSymbolAddress(&p, g_m16); __half* m16 = (__half*)p;
    cudaGetSymbolAddress(&p, g_zero);float* zerob= (float*)p;

    const dim3 blk(256);

    run_cvt(x,  x16, (size_t)NTOK * E_DIM);
    run_cvt(w1, w1h, (size_t)NEXP * FF * E_DIM);
    run_cvt(w2, w2h, (size_t)NEXP * E_DIM * FF);

    // FFN stage 1 (big mbarrier engine, z = expert)
    mma_gemm_big<1><<<dim3(FF / 128, NTOK / 256, NEXP), blk, BIG_SMEM>>>(
        x16, E_DIM, w1h, E_DIM, b1,
        h16, FF, E_DIM,
        0, (size_t)FF * E_DIM, (size_t)NTOK * FF, FF);

    run_cvt(ipw, ipwh, (size_t)3 * E_DIM * E_DIM);

    // FFN stage 2 (big mbarrier engine, z = expert); eo expert-interleaved
    mma_gemm_big<0><<<dim3(E_DIM / 128, NTOK / 256, NEXP), blk, BIG_SMEM>>>(
        h16, FF, w2h, FF, b2,
        eo16, NEXP * E_DIM, FF,
        (size_t)NTOK * FF, (size_t)E_DIM * FF, (size_t)E_DIM, E_DIM);

    transpose_wk_kernel<<<dim3(32, 32), dim3(32, 8)>>>(ipw + (size_t)E_DIM * E_DIM, wkT);

    // q projection for expert_id slice only (fp16 out)
    mma_gemm<0, 1, 128><<<dim3(E_DIM / 128, NTOK / 128, 1), blk, SMALL_SMEM>>>(
        eo16, NEXP * E_DIM, ipwh, E_DIM, ipb,
        nullptr, q16, E_DIM, E_DIM, eid, E_DIM, 0, 0, 0, 0);

    // qk[t,h,:] = q[t,h,:] @ wk_h  (z = head, K = 64)
    mma_gemm<0, 1, 128><<<dim3(E_DIM / 128, NTOK / 128, HEADS), blk, SMALL_SMEM>>>(
        q16, E_DIM, wkT, E_DIM, zerob,
        nullptr, qk16, HEADS * E_DIM, DHEAD, nullptr, 0,
        (size_t)DHEAD, (size_t)DHEAD, (size_t)E_DIM, 0);

    // attention: logits = (qk.eo + q.bk)*scale + mask; softmax; mix -> m[t,h,:]
    attn_mix_kernel<<<NTOK, 512>>>(qk16, q16, eo16, ipb, m16, eid);

    // block-diagonal v projection: o[t, h*64+d] = m[t,h,:] @ wv_h^T + bv_h  (z = head)
    mma_gemm<0, 1, 64><<<dim3(1, NTOK / 128, HEADS), blk, 3 * (PLANE128 + 64 * PITCH)>>>(
        m16, HEADS * E_DIM,
        ipwh + (size_t)2 * E_DIM * E_DIM, E_DIM, ipb + 2 * E_DIM,
        nullptr, o16, E_DIM, E_DIM, nullptr, 0,
        (size_t)E_DIM, (size_t)DHEAD * E_DIM, (size_t)DHEAD, DHEAD);

    run_cvt(ow, owh, (size_t)E_DIM * E_DIM);

    // output projection -> d_out (fp32)
    mma_gemm<0, 0, 128><<<dim3(E_DIM / 128, NTOK / 128, 1), blk, SMALL_SMEM>>>(
        o16, E_DIM, owh, E_DIM, ob,
        out, nullptr, E_DIM, E_DIM, nullptr, 0, 0, 0, 0, 0);
}